// round 1
// baseline (speedup 1.0000x reference)
#include <cuda_runtime.h>
#include <math.h>

// Problem constants
#define BATCH 8
#define CHN 128
#define HH 56
#define WW 56
#define NPTS 65536
#define HID 64
#define MAPN 64
#define PTS_PER_BLK 128
#define FEAT_STRIDE 132   // 128 + 4 pad: float4 accesses conflict-free, 16B aligned rows

// Transposed features scratch: (B, H, W, C) fp32
__device__ float g_tf[BATCH * HH * WW * CHN];

// ---------------------------------------------------------------------------
// Kernel 1: (B,C,H,W) -> (B,H,W,C) tiled transpose
// ---------------------------------------------------------------------------
__global__ void transpose_kernel(const float* __restrict__ f) {
    __shared__ float tile[32][33];
    const int b  = blockIdx.z;
    const int c0 = blockIdx.y << 5;
    const int s0 = blockIdx.x << 5;   // spatial index (h*W + w), 3136 total
    const int tx = threadIdx.x, ty = threadIdx.y;
    // coalesced read along spatial
    tile[ty][tx] = f[(size_t)(b * CHN + c0 + ty) * 3136 + (s0 + tx)];
    __syncthreads();
    // coalesced write along channel
    g_tf[(size_t)(b * 3136 + s0 + ty) * CHN + (c0 + tx)] = tile[tx][ty];
}

// ---------------------------------------------------------------------------
// Fused decoder
// ---------------------------------------------------------------------------
__device__ __forceinline__ void accumRow(float* h, float f, const float* w) {
    const float4* wv = (const float4*)w;
#pragma unroll
    for (int j4 = 0; j4 < 16; ++j4) {
        float4 ww = wv[j4];
        h[4 * j4 + 0] = fmaf(f, ww.x, h[4 * j4 + 0]);
        h[4 * j4 + 1] = fmaf(f, ww.y, h[4 * j4 + 1]);
        h[4 * j4 + 2] = fmaf(f, ww.z, h[4 * j4 + 2]);
        h[4 * j4 + 3] = fmaf(f, ww.w, h[4 * j4 + 3]);
    }
}

__global__ __launch_bounds__(PTS_PER_BLK, 1)
void decoder_kernel(const float* __restrict__ points,
                    const float* __restrict__ kmat,
                    const float* __restrict__ rtm,
                    const float* __restrict__ Bg,
                    const float* __restrict__ W1, const float* __restrict__ b1,
                    const float* __restrict__ W2, const float* __restrict__ b2,
                    const float* __restrict__ W3, const float* __restrict__ b3,
                    const float* __restrict__ W4, const float* __restrict__ b4,
                    float* __restrict__ out) {
    extern __shared__ float sm[];
    float* sW1 = sm;                 // 256*64 = 16384
    float* sW2 = sW1 + 16384;        // 4096
    float* sW3 = sW2 + 4096;         // 4096
    float* sW4 = sW3 + 4096;         // 64
    float* sB1 = sW4 + 64;           // 64
    float* sB2 = sB1 + 64;           // 64
    float* sB3 = sB2 + 64;           // 64
    float* sBg = sB3 + 64;           // 192
    float* sFeat = sBg + 192;        // 128 * 132

    const int tid = threadIdx.x;

    // ---- stage weights to smem (broadcast reads later) ----
    {
        float4* d = (float4*)sW1; const float4* s = (const float4*)W1;
        for (int i = tid; i < 4096; i += PTS_PER_BLK) d[i] = s[i];
        d = (float4*)sW2; s = (const float4*)W2;
        for (int i = tid; i < 1024; i += PTS_PER_BLK) d[i] = s[i];
        d = (float4*)sW3; s = (const float4*)W3;
        for (int i = tid; i < 1024; i += PTS_PER_BLK) d[i] = s[i];
        if (tid < 16) ((float4*)sW4)[tid] = ((const float4*)W4)[tid];
        if (tid < 64) { sB1[tid] = b1[tid]; sB2[tid] = b2[tid]; sB3[tid] = b3[tid]; }
        if (tid < 96) ((float2*)sBg)[tid] = ((const float2*)Bg)[tid];
    }

    // ---- per-point projection ----
    const int p = blockIdx.x * PTS_PER_BLK + tid;   // global point id
    const int b = p >> 16;                          // 65536 pts per batch
    const float* pt = points + (size_t)p * 3;
    const float px = pt[0], py = pt[1], pz = pt[2];
    const float* R = rtm + b * 12;
    const float* K = kmat + b * 9;
    const float cx = fmaf(R[0], px, fmaf(R[1], py, fmaf(R[2],  pz, R[3])));
    const float cy = fmaf(R[4], px, fmaf(R[5], py, fmaf(R[6],  pz, R[7])));
    const float cz = fmaf(R[8], px, fmaf(R[9], py, fmaf(R[10], pz, R[11])));
    const float ix = fmaf(K[0], cx, fmaf(K[1], cy, K[2] * cz));
    const float iy = fmaf(K[3], cx, fmaf(K[4], cy, K[5] * cz));
    const float iz = fmaf(K[6], cx, fmaf(K[7], cy, K[8] * cz));
    const bool  pos = (iz > 0.0f);
    const float valid = pos ? 1.0f : 0.0f;
    const float zz = iz + 1e-8f;
    // grid_sample unnormalization collapses algebraically to x=u, y=v
    const float u = ix / zz, v = iy / zz;
    const float xf = floorf(u), yf = floorf(v);
    float fx = u - xf, fy = v - yf;
    int x0 = (int)xf, y0 = (int)yf;
    if (!pos) { x0 = -100000; y0 = -100000; fx = 0.0f; fy = 0.0f; }

    // ---- warp-cooperative bilinear gather: lane l owns channels [4l,4l+4) ----
    const int lane = tid & 31;
    const int wb = tid & ~31;
    const float* baseb = g_tf + (size_t)b * 3136 * CHN + lane * 4;
#pragma unroll 1
    for (int i = 0; i < 32; ++i) {
        const float gfx = __shfl_sync(0xffffffffu, fx, i);
        const float gfy = __shfl_sync(0xffffffffu, fy, i);
        const float gv  = __shfl_sync(0xffffffffu, valid, i);
        const int   gx  = __shfl_sync(0xffffffffu, x0, i);
        const int   gy  = __shfl_sync(0xffffffffu, y0, i);
        const float ax = 1.0f - gfx, ay = 1.0f - gfy;
        const float w00 = ax * ay * gv;
        const float w10 = gfx * ay * gv;
        const float w01 = ax * gfy * gv;
        const float w11 = gfx * gfy * gv;
        const bool x0in = (gx >= 0) && (gx < WW);
        const bool x1in = (gx >= -1) && (gx < WW - 1);
        const bool y0in = (gy >= 0) && (gy < HH);
        const bool y1in = (gy >= -1) && (gy < HH - 1);
        const int rowoff = (gy * WW + gx) * CHN;
        float4 acc = make_float4(0.f, 0.f, 0.f, 0.f);
        if (x0in && y0in) {
            float4 t = *(const float4*)(baseb + rowoff);
            acc.x = fmaf(w00, t.x, acc.x); acc.y = fmaf(w00, t.y, acc.y);
            acc.z = fmaf(w00, t.z, acc.z); acc.w = fmaf(w00, t.w, acc.w);
        }
        if (x1in && y0in) {
            float4 t = *(const float4*)(baseb + rowoff + CHN);
            acc.x = fmaf(w10, t.x, acc.x); acc.y = fmaf(w10, t.y, acc.y);
            acc.z = fmaf(w10, t.z, acc.z); acc.w = fmaf(w10, t.w, acc.w);
        }
        if (x0in && y1in) {
            float4 t = *(const float4*)(baseb + rowoff + WW * CHN);
            acc.x = fmaf(w01, t.x, acc.x); acc.y = fmaf(w01, t.y, acc.y);
            acc.z = fmaf(w01, t.z, acc.z); acc.w = fmaf(w01, t.w, acc.w);
        }
        if (x1in && y1in) {
            float4 t = *(const float4*)(baseb + rowoff + (WW + 1) * CHN);
            acc.x = fmaf(w11, t.x, acc.x); acc.y = fmaf(w11, t.y, acc.y);
            acc.z = fmaf(w11, t.z, acc.z); acc.w = fmaf(w11, t.w, acc.w);
        }
        *(float4*)(sFeat + (wb + i) * FEAT_STRIDE + lane * 4) = acc;
    }
    __syncthreads();   // weights + (warp-local) feats ready

    // ---- MLP layer 1: 256 -> 64 ----
    float h[64];
#pragma unroll
    for (int j = 0; j < 64; ++j) h[j] = sB1[j];

    const float4* frow = (const float4*)(sFeat + tid * FEAT_STRIDE);
#pragma unroll 2
    for (int cg = 0; cg < 32; ++cg) {
        float4 f4 = frow[cg];
        const float* wbase = sW1 + cg * 256;
        accumRow(h, f4.x, wbase);
        accumRow(h, f4.y, wbase + 64);
        accumRow(h, f4.z, wbase + 128);
        accumRow(h, f4.w, wbase + 192);
    }

    // Fourier part: rows 128..191 = sin, 192..255 = cos
    const float TWOPI = 6.283185307179586f;
#pragma unroll 1
    for (int m = 0; m < 64; ++m) {
        float xp = TWOPI * fmaf(px, sBg[m * 3],
                         fmaf(py, sBg[m * 3 + 1], pz * sBg[m * 3 + 2]));
        float s, c;
        sincosf(xp, &s, &c);
        accumRow(h, s, sW1 + (128 + m) * 64);
        accumRow(h, c, sW1 + (192 + m) * 64);
    }

    // relu + spill h1 to own smem row (reuse sFeat)
    float* myrow = sFeat + tid * FEAT_STRIDE;
#pragma unroll
    for (int j4 = 0; j4 < 16; ++j4) {
        float4 o;
        o.x = fmaxf(h[4 * j4 + 0], 0.f);
        o.y = fmaxf(h[4 * j4 + 1], 0.f);
        o.z = fmaxf(h[4 * j4 + 2], 0.f);
        o.w = fmaxf(h[4 * j4 + 3], 0.f);
        ((float4*)myrow)[j4] = o;
    }

    // ---- layer 2 ----
#pragma unroll
    for (int j = 0; j < 64; ++j) h[j] = sB2[j];
#pragma unroll 2
    for (int kg = 0; kg < 16; ++kg) {
        float4 f4 = ((const float4*)myrow)[kg];
        const float* wbase = sW2 + kg * 256;
        accumRow(h, f4.x, wbase);
        accumRow(h, f4.y, wbase + 64);
        accumRow(h, f4.z, wbase + 128);
        accumRow(h, f4.w, wbase + 192);
    }
#pragma unroll
    for (int j4 = 0; j4 < 16; ++j4) {
        float4 o;
        o.x = fmaxf(h[4 * j4 + 0], 0.f);
        o.y = fmaxf(h[4 * j4 + 1], 0.f);
        o.z = fmaxf(h[4 * j4 + 2], 0.f);
        o.w = fmaxf(h[4 * j4 + 3], 0.f);
        ((float4*)myrow)[j4] = o;
    }

    // ---- layer 3 ----
#pragma unroll
    for (int j = 0; j < 64; ++j) h[j] = sB3[j];
#pragma unroll 2
    for (int kg = 0; kg < 16; ++kg) {
        float4 f4 = ((const float4*)myrow)[kg];
        const float* wbase = sW3 + kg * 256;
        accumRow(h, f4.x, wbase);
        accumRow(h, f4.y, wbase + 64);
        accumRow(h, f4.z, wbase + 128);
        accumRow(h, f4.w, wbase + 192);
    }

    // ---- layer 4: relu(h3) . W4 + b4 ----
    float acc = b4[0];
#pragma unroll
    for (int j = 0; j < 64; ++j) acc = fmaf(fmaxf(h[j], 0.f), sW4[j], acc);
    out[p] = acc;
}

// ---------------------------------------------------------------------------
// Launch
// ---------------------------------------------------------------------------
extern "C" void kernel_launch(void* const* d_in, const int* in_sizes, int n_in,
                              void* d_out, int out_size) {
    const float* features = (const float*)d_in[0];
    const float* points   = (const float*)d_in[1];
    const float* kmat     = (const float*)d_in[2];
    const float* rtm      = (const float*)d_in[3];
    const float* Bg       = (const float*)d_in[4];
    const float* W1 = (const float*)d_in[5];
    const float* b1 = (const float*)d_in[6];
    const float* W2 = (const float*)d_in[7];
    const float* b2 = (const float*)d_in[8];
    const float* W3 = (const float*)d_in[9];
    const float* b3 = (const float*)d_in[10];
    const float* W4 = (const float*)d_in[11];
    const float* b4 = (const float*)d_in[12];

    // transpose features into (B,H,W,C) scratch
    dim3 tb(32, 32);
    dim3 tg(3136 / 32, CHN / 32, BATCH);   // (98, 4, 8)
    transpose_kernel<<<tg, tb>>>(features);

    const int smem_bytes = (16384 + 4096 + 4096 + 64 + 64 + 64 + 64 + 192 +
                            PTS_PER_BLK * FEAT_STRIDE) * (int)sizeof(float);  // 167,680
    cudaFuncSetAttribute(decoder_kernel,
                         cudaFuncAttributeMaxDynamicSharedMemorySize, smem_bytes);

    const int nblocks = (BATCH * NPTS) / PTS_PER_BLK;   // 4096
    decoder_kernel<<<nblocks, PTS_PER_BLK, smem_bytes>>>(
        points, kmat, rtm, Bg, W1, b1, W2, b2, W3, b3, W4, b4, (float*)d_out);
}

// round 2
// speedup vs baseline: 1.2479x; 1.2479x over previous
#include <cuda_runtime.h>
#include <math.h>

// Problem constants
#define BATCH 8
#define CHN 128
#define HH 56
#define WW 56
#define NPTS 65536
#define HID 64
#define PTS_PER_BLK 128
#define NTHREADS 256
#define FEAT_STRIDE 132   // 128 + 4 pad: float4 accesses conflict-free

// Transposed features scratch: (B, H, W, C) fp32
__device__ float g_tf[BATCH * HH * WW * CHN];

// ---------------------------------------------------------------------------
// Kernel 1: (B,C,H,W) -> (B,H,W,C) tiled transpose
// ---------------------------------------------------------------------------
__global__ void transpose_kernel(const float* __restrict__ f) {
    __shared__ float tile[32][33];
    const int b  = blockIdx.z;
    const int c0 = blockIdx.y << 5;
    const int s0 = blockIdx.x << 5;
    const int tx = threadIdx.x, ty = threadIdx.y;
    tile[ty][tx] = f[(size_t)(b * CHN + c0 + ty) * 3136 + (s0 + tx)];
    __syncthreads();
    g_tf[(size_t)(b * 3136 + s0 + ty) * CHN + (c0 + tx)] = tile[tx][ty];
}

// ---------------------------------------------------------------------------
// accumulate 32 outputs: h[j] += f * w[j], w = 32 consecutive floats in smem
// ---------------------------------------------------------------------------
__device__ __forceinline__ void accumRow32(float* h, float f, const float* w) {
    const float4* wv = (const float4*)w;
#pragma unroll
    for (int j4 = 0; j4 < 8; ++j4) {
        float4 ww = wv[j4];
        h[4 * j4 + 0] = fmaf(f, ww.x, h[4 * j4 + 0]);
        h[4 * j4 + 1] = fmaf(f, ww.y, h[4 * j4 + 1]);
        h[4 * j4 + 2] = fmaf(f, ww.z, h[4 * j4 + 2]);
        h[4 * j4 + 3] = fmaf(f, ww.w, h[4 * j4 + 3]);
    }
}

// ---------------------------------------------------------------------------
// Fused decoder: 128 points per CTA, 256 threads (2 threads/point, 32 outs each)
// ---------------------------------------------------------------------------
__global__ __launch_bounds__(NTHREADS, 1)
void decoder_kernel(const float* __restrict__ points,
                    const float* __restrict__ kmat,
                    const float* __restrict__ rtm,
                    const float* __restrict__ Bg,
                    const float* __restrict__ W1, const float* __restrict__ b1,
                    const float* __restrict__ W2, const float* __restrict__ b2,
                    const float* __restrict__ W3, const float* __restrict__ b3,
                    const float* __restrict__ W4, const float* __restrict__ b4,
                    float* __restrict__ out) {
    extern __shared__ float sm[];
    float* sW1 = sm;                  // 16384
    float* sW2 = sW1 + 16384;         // 4096
    float* sW3 = sW2 + 4096;          // 4096
    float* sW4 = sW3 + 4096;          // 64
    float* sB1 = sW4 + 64;            // 64
    float* sB2 = sB1 + 64;            // 64
    float* sB3 = sB2 + 64;            // 64
    float* sBg = sB3 + 64;            // 192
    float* sFeat = sBg + 192;         // 128 * 132 = 16896
    float* sFx = sFeat + PTS_PER_BLK * FEAT_STRIDE;  // 128
    float* sFy = sFx + 128;           // 128
    float* sVa = sFy + 128;           // 128
    int*   sX0 = (int*)(sVa + 128);   // 128
    int*   sY0 = sX0 + 128;           // 128
    float* sPart = (float*)(sY0 + 128); // 256

    const int tid  = threadIdx.x;
    const int pid  = tid & 127;       // point within block
    const int half = tid >> 7;        // 0: outputs 0..31, 1: outputs 32..63
    const int hb   = half * 32;

    // ---- stage weights to smem ----
    {
        float4* d = (float4*)sW1; const float4* s = (const float4*)W1;
        for (int i = tid; i < 4096; i += NTHREADS) d[i] = s[i];
        d = (float4*)sW2; s = (const float4*)W2;
        for (int i = tid; i < 1024; i += NTHREADS) d[i] = s[i];
        d = (float4*)sW3; s = (const float4*)W3;
        for (int i = tid; i < 1024; i += NTHREADS) d[i] = s[i];
        if (tid < 16) ((float4*)sW4)[tid] = ((const float4*)W4)[tid];
        if (tid < 64) { sB1[tid] = b1[tid]; sB2[tid] = b2[tid]; sB3[tid] = b3[tid]; }
        if (tid < 96) ((float2*)sBg)[tid] = ((const float2*)Bg)[tid];
    }

    // ---- per-point projection (half 0 threads write params) ----
    const int p = blockIdx.x * PTS_PER_BLK + pid;
    const int b = p >> 16;
    const float* pt = points + (size_t)p * 3;
    const float px = pt[0], py = pt[1], pz = pt[2];
    if (half == 0) {
        const float* R = rtm + b * 12;
        const float* K = kmat + b * 9;
        const float cx = fmaf(R[0], px, fmaf(R[1], py, fmaf(R[2],  pz, R[3])));
        const float cy = fmaf(R[4], px, fmaf(R[5], py, fmaf(R[6],  pz, R[7])));
        const float cz = fmaf(R[8], px, fmaf(R[9], py, fmaf(R[10], pz, R[11])));
        const float ix = fmaf(K[0], cx, fmaf(K[1], cy, K[2] * cz));
        const float iy = fmaf(K[3], cx, fmaf(K[4], cy, K[5] * cz));
        const float iz = fmaf(K[6], cx, fmaf(K[7], cy, K[8] * cz));
        const bool  pos = (iz > 0.0f);
        const float zz = iz + 1e-8f;
        const float u = __fdividef(ix, zz), v = __fdividef(iy, zz);
        const float xf = floorf(u), yf = floorf(v);
        float fx = u - xf, fy = v - yf;
        int x0 = (int)xf, y0 = (int)yf;
        if (!pos) { x0 = -100000; y0 = -100000; fx = 0.0f; fy = 0.0f; }
        sFx[pid] = fx; sFy[pid] = fy; sVa[pid] = pos ? 1.0f : 0.0f;
        sX0[pid] = x0; sY0[pid] = y0;
    }
    __syncthreads();

    // ---- warp-cooperative bilinear gather: 8 warps x 16 points each ----
    {
        const int w    = tid >> 5;
        const int lane = tid & 31;
        const int q0   = w << 4;                       // first point for this warp
        // batch of this warp's points (all same batch since 128 | 65536 tiles)
        const int gb = (blockIdx.x * PTS_PER_BLK) >> 16;
        const float* baseb = g_tf + (size_t)gb * 3136 * CHN + lane * 4;
#pragma unroll 1
        for (int i = 0; i < 16; ++i) {
            const int q = q0 + i;
            const float gfx = sFx[q], gfy = sFy[q], gv = sVa[q];
            const int gx = sX0[q], gy = sY0[q];
            const float ax = 1.0f - gfx, ay = 1.0f - gfy;
            const float w00 = ax * ay * gv;
            const float w10 = gfx * ay * gv;
            const float w01 = ax * gfy * gv;
            const float w11 = gfx * gfy * gv;
            const bool x0in = (gx >= 0) && (gx < WW);
            const bool x1in = (gx >= -1) && (gx < WW - 1);
            const bool y0in = (gy >= 0) && (gy < HH);
            const bool y1in = (gy >= -1) && (gy < HH - 1);
            const int rowoff = (gy * WW + gx) * CHN;
            float4 acc = make_float4(0.f, 0.f, 0.f, 0.f);
            if (x0in && y0in) {
                float4 t = *(const float4*)(baseb + rowoff);
                acc.x = fmaf(w00, t.x, acc.x); acc.y = fmaf(w00, t.y, acc.y);
                acc.z = fmaf(w00, t.z, acc.z); acc.w = fmaf(w00, t.w, acc.w);
            }
            if (x1in && y0in) {
                float4 t = *(const float4*)(baseb + rowoff + CHN);
                acc.x = fmaf(w10, t.x, acc.x); acc.y = fmaf(w10, t.y, acc.y);
                acc.z = fmaf(w10, t.z, acc.z); acc.w = fmaf(w10, t.w, acc.w);
            }
            if (x0in && y1in) {
                float4 t = *(const float4*)(baseb + rowoff + WW * CHN);
                acc.x = fmaf(w01, t.x, acc.x); acc.y = fmaf(w01, t.y, acc.y);
                acc.z = fmaf(w01, t.z, acc.z); acc.w = fmaf(w01, t.w, acc.w);
            }
            if (x1in && y1in) {
                float4 t = *(const float4*)(baseb + rowoff + (WW + 1) * CHN);
                acc.x = fmaf(w11, t.x, acc.x); acc.y = fmaf(w11, t.y, acc.y);
                acc.z = fmaf(w11, t.z, acc.z); acc.w = fmaf(w11, t.w, acc.w);
            }
            *(float4*)(sFeat + q * FEAT_STRIDE + lane * 4) = acc;
        }
    }
    __syncthreads();

    // ---- MLP layer 1: 256 -> 64, this thread computes outputs [hb, hb+32) ----
    float h[32];
#pragma unroll
    for (int j = 0; j < 32; ++j) h[j] = sB1[hb + j];

    const float4* frow = (const float4*)(sFeat + pid * FEAT_STRIDE);
#pragma unroll 4
    for (int cg = 0; cg < 32; ++cg) {
        float4 f4 = frow[cg];
        const float* wbase = sW1 + cg * 256 + hb;
        accumRow32(h, f4.x, wbase);
        accumRow32(h, f4.y, wbase + 64);
        accumRow32(h, f4.z, wbase + 128);
        accumRow32(h, f4.w, wbase + 192);
    }

    // Fourier part: W1 rows 128..191 = sin, 192..255 = cos
    const float TWOPI = 6.283185307179586f;
#pragma unroll 2
    for (int m = 0; m < 64; ++m) {
        float xp = TWOPI * fmaf(px, sBg[m * 3],
                         fmaf(py, sBg[m * 3 + 1], pz * sBg[m * 3 + 2]));
        float s = __sinf(xp);
        float c = __cosf(xp);
        accumRow32(h, s, sW1 + (128 + m) * 64 + hb);
        accumRow32(h, c, sW1 + (192 + m) * 64 + hb);
    }
    __syncthreads();   // everyone done reading sFeat rows

    // relu + spill h1 halves into the point's feat row (cols hb..hb+32)
    float* myrow = sFeat + pid * FEAT_STRIDE + hb;
#pragma unroll
    for (int j4 = 0; j4 < 8; ++j4) {
        float4 o;
        o.x = fmaxf(h[4 * j4 + 0], 0.f);
        o.y = fmaxf(h[4 * j4 + 1], 0.f);
        o.z = fmaxf(h[4 * j4 + 2], 0.f);
        o.w = fmaxf(h[4 * j4 + 3], 0.f);
        ((float4*)myrow)[j4] = o;
    }
    __syncthreads();

    // ---- layer 2: 64 -> 64 (half) ----
#pragma unroll
    for (int j = 0; j < 32; ++j) h[j] = sB2[hb + j];
    const float4* hrow = (const float4*)(sFeat + pid * FEAT_STRIDE);
#pragma unroll 4
    for (int kg = 0; kg < 16; ++kg) {
        float4 f4 = hrow[kg];
        const float* wbase = sW2 + kg * 256 + hb;
        accumRow32(h, f4.x, wbase);
        accumRow32(h, f4.y, wbase + 64);
        accumRow32(h, f4.z, wbase + 128);
        accumRow32(h, f4.w, wbase + 192);
    }
    __syncthreads();
#pragma unroll
    for (int j4 = 0; j4 < 8; ++j4) {
        float4 o;
        o.x = fmaxf(h[4 * j4 + 0], 0.f);
        o.y = fmaxf(h[4 * j4 + 1], 0.f);
        o.z = fmaxf(h[4 * j4 + 2], 0.f);
        o.w = fmaxf(h[4 * j4 + 3], 0.f);
        ((float4*)myrow)[j4] = o;
    }
    __syncthreads();

    // ---- layer 3: 64 -> 64 (half) ----
#pragma unroll
    for (int j = 0; j < 32; ++j) h[j] = sB3[hb + j];
#pragma unroll 4
    for (int kg = 0; kg < 16; ++kg) {
        float4 f4 = hrow[kg];
        const float* wbase = sW3 + kg * 256 + hb;
        accumRow32(h, f4.x, wbase);
        accumRow32(h, f4.y, wbase + 64);
        accumRow32(h, f4.z, wbase + 128);
        accumRow32(h, f4.w, wbase + 192);
    }

    // ---- layer 4: partial dot over this half's 32 relu(h3) values ----
    float acc = 0.0f;
#pragma unroll
    for (int j = 0; j < 32; ++j) acc = fmaf(fmaxf(h[j], 0.f), sW4[hb + j], acc);
    sPart[tid] = acc;
    __syncthreads();
    if (half == 0) {
        out[p] = sPart[pid] + sPart[pid + 128] + b4[0];
    }
}

// ---------------------------------------------------------------------------
// Launch
// ---------------------------------------------------------------------------
extern "C" void kernel_launch(void* const* d_in, const int* in_sizes, int n_in,
                              void* d_out, int out_size) {
    const float* features = (const float*)d_in[0];
    const float* points   = (const float*)d_in[1];
    const float* kmat     = (const float*)d_in[2];
    const float* rtm      = (const float*)d_in[3];
    const float* Bg       = (const float*)d_in[4];
    const float* W1 = (const float*)d_in[5];
    const float* b1 = (const float*)d_in[6];
    const float* W2 = (const float*)d_in[7];
    const float* b2 = (const float*)d_in[8];
    const float* W3 = (const float*)d_in[9];
    const float* b3 = (const float*)d_in[10];
    const float* W4 = (const float*)d_in[11];
    const float* b4 = (const float*)d_in[12];

    dim3 tb(32, 32);
    dim3 tg(3136 / 32, CHN / 32, BATCH);
    transpose_kernel<<<tg, tb>>>(features);

    const int smem_floats = 16384 + 4096 + 4096 + 64 + 64 + 64 + 64 + 192 +
                            PTS_PER_BLK * FEAT_STRIDE + 128 * 5 + 256;
    const int smem_bytes = smem_floats * (int)sizeof(float);
    cudaFuncSetAttribute(decoder_kernel,
                         cudaFuncAttributeMaxDynamicSharedMemorySize, smem_bytes);

    const int nblocks = (BATCH * NPTS) / PTS_PER_BLK;   // 4096
    decoder_kernel<<<nblocks, NTHREADS, smem_bytes>>>(
        points, kmat, rtm, Bg, W1, b1, W2, b2, W3, b3, W4, b4, (float*)d_out);
}

// round 4
// speedup vs baseline: 3.6699x; 2.9408x over previous
#include <cuda_runtime.h>
#include <math.h>
#include <stdint.h>

#define BATCH 8
#define CHN 128
#define HH 56
#define WW 56
#define TILE_PTS 128
#define NTHREADS 512
#define NTILES 4096
#define GRID_CTAS 148

#define A_STRIDE 260     // 256 + 4 pad; stride%8==4 -> conflict-free frag loads
#define W1_STRIDE 260
#define W23_STRIDE 68    // 64 + 4 pad

// float-index offsets in dynamic smem
#define FOFF_A     0                      // 128 x 260
#define FOFF_W1    (128 * A_STRIDE)       // 64 x 260
#define FOFF_W23   (FOFF_W1 + 64 * W1_STRIDE)   // 64 x 68
#define FOFF_MISC  (FOFF_W23 + 64 * W23_STRIDE)
#define MI_B1   0
#define MI_B2   64
#define MI_B3   128
#define MI_W4   192
#define MI_BG   256      // 192 floats
#define MI_FX   448
#define MI_FY   576
#define MI_VA   704
#define MI_X0   832
#define MI_Y0   960
#define MI_PART 1088     // 256 floats
#define SMEM_TOTAL ((FOFF_MISC + 1344) * 4)   // 222,464 bytes

// ---------------- globals ----------------
__device__ float g_tf[BATCH * HH * WW * CHN];   // (B,H,W,C) features
__device__ float g_W1T[64 * W1_STRIDE];         // n-major padded tf32 images
__device__ float g_W2T[64 * W23_STRIDE];
__device__ float g_W3T[64 * W23_STRIDE];

__device__ __forceinline__ float to_tf32(float x) {
    uint32_t r;
    asm("cvt.rna.tf32.f32 %0, %1;" : "=r"(r) : "f"(x));
    return __uint_as_float(r);
}

__device__ __forceinline__ void mma16n8k8(float* d, const uint32_t* a, uint32_t b0, uint32_t b1) {
    asm volatile(
        "mma.sync.aligned.m16n8k8.row.col.f32.tf32.tf32.f32 "
        "{%0,%1,%2,%3}, {%4,%5,%6,%7}, {%8,%9}, {%0,%1,%2,%3};"
        : "+f"(d[0]), "+f"(d[1]), "+f"(d[2]), "+f"(d[3])
        : "r"(a[0]), "r"(a[1]), "r"(a[2]), "r"(a[3]), "r"(b0), "r"(b1));
}

// ---------------------------------------------------------------------------
// Kernel 1: (B,C,H,W) -> (B,H,W,C) tiled transpose
// ---------------------------------------------------------------------------
__global__ void transpose_kernel(const float* __restrict__ f) {
    __shared__ float tile[32][33];
    const int b  = blockIdx.z;
    const int c0 = blockIdx.y << 5;
    const int s0 = blockIdx.x << 5;
    const int tx = threadIdx.x, ty = threadIdx.y;
    tile[ty][tx] = f[(size_t)(b * CHN + c0 + ty) * 3136 + (s0 + tx)];
    __syncthreads();
    g_tf[(size_t)(b * 3136 + s0 + ty) * CHN + (c0 + tx)] = tile[tx][ty];
}

// ---------------------------------------------------------------------------
// Kernel 2: transpose + pad + tf32-round weights into global images (n-major)
// ---------------------------------------------------------------------------
__global__ void prep_weights_kernel(const float* __restrict__ W1,
                                    const float* __restrict__ W2,
                                    const float* __restrict__ W3) {
    const int tid = threadIdx.x;
    for (int i = tid; i < 64 * 256; i += 256) {
        int n = i & 63, k = i >> 6;
        g_W1T[n * W1_STRIDE + k] = to_tf32(W1[k * 64 + n]);
    }
    for (int i = tid; i < 64 * 64; i += 256) {
        int n = i & 63, k = i >> 6;
        g_W2T[n * W23_STRIDE + k] = to_tf32(W2[k * 64 + n]);
        g_W3T[n * W23_STRIDE + k] = to_tf32(W3[k * 64 + n]);
    }
}

// ---------------------------------------------------------------------------
// Kernel 3: persistent fused decoder (mma.sync tf32 MLP)
// ---------------------------------------------------------------------------
__global__ __launch_bounds__(NTHREADS, 1)
void decoder_kernel(const float* __restrict__ points,
                    const float* __restrict__ kmat,
                    const float* __restrict__ rtm,
                    const float* __restrict__ Bg,
                    const float* __restrict__ b1,
                    const float* __restrict__ b2,
                    const float* __restrict__ b3,
                    const float* __restrict__ W4,
                    const float* __restrict__ b4,
                    float* __restrict__ out) {
    extern __shared__ float sm[];
    float* sA   = sm + FOFF_A;
    float* sW1  = sm + FOFF_W1;
    float* sW23 = sm + FOFF_W23;
    float* sMi  = sm + FOFF_MISC;
    float* sB1 = sMi + MI_B1;
    float* sB2 = sMi + MI_B2;
    float* sB3 = sMi + MI_B3;
    float* sW4 = sMi + MI_W4;
    float* sBg = sMi + MI_BG;
    float* sFx = sMi + MI_FX;
    float* sFy = sMi + MI_FY;
    float* sVa = sMi + MI_VA;
    int*   sX0 = (int*)(sMi + MI_X0);
    int*   sY0 = (int*)(sMi + MI_Y0);
    float* sPart = sMi + MI_PART;

    const int tid  = threadIdx.x;
    const int wid  = tid >> 5;
    const int lane = tid & 31;
    const int pid  = tid & 127;

    // mma role decomposition
    const int mt = wid >> 1;          // m-tile 0..7 (rows mt*16 .. +16)
    const int nh = wid & 1;           // col half: cols nh*32 .. +32
    const int g  = lane >> 2;         // 0..7
    const int t  = lane & 3;          // 0..3
    const int row0 = mt * 16 + g;
    const int row1 = row0 + 8;

    // ---- one-time init ----
    {
        const float4* s = (const float4*)g_W1T;
        float4* d = (float4*)sW1;
        for (int i = tid; i < 64 * W1_STRIDE / 4; i += NTHREADS) d[i] = s[i];
    }
    if (tid < 64) {
        sB1[tid] = b1[tid]; sB2[tid] = b2[tid]; sB3[tid] = b3[tid];
        sW4[tid] = W4[tid];
    }
    if (tid < 96) ((float2*)sBg)[tid] = ((const float2*)Bg)[tid];
    const float b4v = b4[0];
    __syncthreads();

    for (int tile = blockIdx.x; tile < NTILES; tile += GRID_CTAS) {
        const int p0 = tile * TILE_PTS;
        const int b  = p0 >> 16;

        // ---- projection (threads 0..127) ----
        const float* pt = points + (size_t)(p0 + pid) * 3;
        const float px = pt[0], py = pt[1], pz = pt[2];
        if (tid < 128) {
            const float* R = rtm + b * 12;
            const float* K = kmat + b * 9;
            const float cx = fmaf(R[0], px, fmaf(R[1], py, fmaf(R[2],  pz, R[3])));
            const float cy = fmaf(R[4], px, fmaf(R[5], py, fmaf(R[6],  pz, R[7])));
            const float cz = fmaf(R[8], px, fmaf(R[9], py, fmaf(R[10], pz, R[11])));
            const float ix = fmaf(K[0], cx, fmaf(K[1], cy, K[2] * cz));
            const float iy = fmaf(K[3], cx, fmaf(K[4], cy, K[5] * cz));
            const float iz = fmaf(K[6], cx, fmaf(K[7], cy, K[8] * cz));
            const bool  pos = (iz > 0.0f);
            const float zz = iz + 1e-8f;
            const float u = __fdividef(ix, zz), v = __fdividef(iy, zz);
            const float xf = floorf(u), yf = floorf(v);
            float fx = u - xf, fy = v - yf;
            int x0 = (int)xf, y0 = (int)yf;
            if (!pos) { x0 = -100000; y0 = -100000; fx = 0.0f; fy = 0.0f; }
            sFx[pid] = fx; sFy[pid] = fy; sVa[pid] = pos ? 1.0f : 0.0f;
            sX0[pid] = x0; sY0[pid] = y0;
        }
        __syncthreads();

        // ---- warp-cooperative bilinear gather -> A cols [0,128) ----
        {
            const int q0 = wid << 3;      // 16 warps x 8 points
            const float* baseb = g_tf + (size_t)b * 3136 * CHN + lane * 4;
#pragma unroll 2
            for (int i = 0; i < 8; ++i) {
                const int q = q0 + i;
                const float gfx = sFx[q], gfy = sFy[q], gv = sVa[q];
                const int gx = sX0[q], gy = sY0[q];
                const float ax = 1.0f - gfx, ay = 1.0f - gfy;
                const float w00 = ax * ay * gv;
                const float w10 = gfx * ay * gv;
                const float w01 = ax * gfy * gv;
                const float w11 = gfx * gfy * gv;
                const bool x0in = (gx >= 0) && (gx < WW);
                const bool x1in = (gx >= -1) && (gx < WW - 1);
                const bool y0in = (gy >= 0) && (gy < HH);
                const bool y1in = (gy >= -1) && (gy < HH - 1);
                const int rowoff = (gy * WW + gx) * CHN;
                float4 acc = make_float4(0.f, 0.f, 0.f, 0.f);
                if (x0in && y0in) {
                    float4 v4 = *(const float4*)(baseb + rowoff);
                    acc.x = fmaf(w00, v4.x, acc.x); acc.y = fmaf(w00, v4.y, acc.y);
                    acc.z = fmaf(w00, v4.z, acc.z); acc.w = fmaf(w00, v4.w, acc.w);
                }
                if (x1in && y0in) {
                    float4 v4 = *(const float4*)(baseb + rowoff + CHN);
                    acc.x = fmaf(w10, v4.x, acc.x); acc.y = fmaf(w10, v4.y, acc.y);
                    acc.z = fmaf(w10, v4.z, acc.z); acc.w = fmaf(w10, v4.w, acc.w);
                }
                if (x0in && y1in) {
                    float4 v4 = *(const float4*)(baseb + rowoff + WW * CHN);
                    acc.x = fmaf(w01, v4.x, acc.x); acc.y = fmaf(w01, v4.y, acc.y);
                    acc.z = fmaf(w01, v4.z, acc.z); acc.w = fmaf(w01, v4.w, acc.w);
                }
                if (x1in && y1in) {
                    float4 v4 = *(const float4*)(baseb + rowoff + (WW + 1) * CHN);
                    acc.x = fmaf(w11, v4.x, acc.x); acc.y = fmaf(w11, v4.y, acc.y);
                    acc.z = fmaf(w11, v4.z, acc.z); acc.w = fmaf(w11, v4.w, acc.w);
                }
                acc.x = to_tf32(acc.x); acc.y = to_tf32(acc.y);
                acc.z = to_tf32(acc.z); acc.w = to_tf32(acc.w);
                *(float4*)(sA + q * A_STRIDE + lane * 4) = acc;
            }
        }

        // ---- Fourier features -> A cols [128,256) ----
        {
            const float TWOPI = 6.283185307179586f;
            const int mg = tid >> 7;              // 0..3, 16 m's each
            float* arow = sA + pid * A_STRIDE;
#pragma unroll 4
            for (int j = 0; j < 16; ++j) {
                const int m = mg * 16 + j;
                float xp = TWOPI * fmaf(px, sBg[m * 3],
                                 fmaf(py, sBg[m * 3 + 1], pz * sBg[m * 3 + 2]));
                arow[128 + m] = to_tf32(__sinf(xp));
                arow[192 + m] = to_tf32(__cosf(xp));
            }
        }

        // ---- stream W2T into shared slot ----
        {
            const float4* s = (const float4*)g_W2T;
            float4* d = (float4*)sW23;
            for (int i = tid; i < 64 * W23_STRIDE / 4; i += NTHREADS) d[i] = s[i];
        }
        __syncthreads();

        // ================= Layer 1: [128x256] @ W1 -> [128x64] =================
        float acc[4][4];
#pragma unroll
        for (int nt = 0; nt < 4; ++nt)
#pragma unroll
            for (int j = 0; j < 4; ++j) acc[nt][j] = 0.0f;
        {
            const uint32_t* Ar0 = (const uint32_t*)(sA + row0 * A_STRIDE + t);
            const uint32_t* Ar1 = (const uint32_t*)(sA + row1 * A_STRIDE + t);
#pragma unroll 4
            for (int kk = 0; kk < 32; ++kk) {
                uint32_t a[4];
                a[0] = Ar0[kk * 8];
                a[1] = Ar1[kk * 8];
                a[2] = Ar0[kk * 8 + 4];
                a[3] = Ar1[kk * 8 + 4];
#pragma unroll
                for (int nt = 0; nt < 4; ++nt) {
                    const int n = nh * 32 + nt * 8 + g;
                    const uint32_t* Bp = (const uint32_t*)(sW1 + n * W1_STRIDE + kk * 8 + t);
                    mma16n8k8(acc[nt], a, Bp[0], Bp[4]);
                }
            }
        }
        __syncthreads();   // all L1 A-reads done

        // relu(acc + b1) -> A cols [0,64)
#pragma unroll
        for (int nt = 0; nt < 4; ++nt) {
            const int col = nh * 32 + nt * 8 + t * 2;
            float2 v0, v1;
            v0.x = to_tf32(fmaxf(acc[nt][0] + sB1[col], 0.f));
            v0.y = to_tf32(fmaxf(acc[nt][1] + sB1[col + 1], 0.f));
            v1.x = to_tf32(fmaxf(acc[nt][2] + sB1[col], 0.f));
            v1.y = to_tf32(fmaxf(acc[nt][3] + sB1[col + 1], 0.f));
            *(float2*)(sA + row0 * A_STRIDE + col) = v0;
            *(float2*)(sA + row1 * A_STRIDE + col) = v1;
        }
        __syncthreads();

        // ================= Layer 2: [128x64] @ W2 =================
#pragma unroll
        for (int nt = 0; nt < 4; ++nt)
#pragma unroll
            for (int j = 0; j < 4; ++j) acc[nt][j] = 0.0f;
        {
            const uint32_t* Ar0 = (const uint32_t*)(sA + row0 * A_STRIDE + t);
            const uint32_t* Ar1 = (const uint32_t*)(sA + row1 * A_STRIDE + t);
#pragma unroll
            for (int kk = 0; kk < 8; ++kk) {
                uint32_t a[4];
                a[0] = Ar0[kk * 8];
                a[1] = Ar1[kk * 8];
                a[2] = Ar0[kk * 8 + 4];
                a[3] = Ar1[kk * 8 + 4];
#pragma unroll
                for (int nt = 0; nt < 4; ++nt) {
                    const int n = nh * 32 + nt * 8 + g;
                    const uint32_t* Bp = (const uint32_t*)(sW23 + n * W23_STRIDE + kk * 8 + t);
                    mma16n8k8(acc[nt], a, Bp[0], Bp[4]);
                }
            }
        }
        // relu(acc + b2) -> A cols [64,128)  (no pre-sync: disjoint from L2 reads)
#pragma unroll
        for (int nt = 0; nt < 4; ++nt) {
            const int col = nh * 32 + nt * 8 + t * 2;
            float2 v0, v1;
            v0.x = to_tf32(fmaxf(acc[nt][0] + sB2[col], 0.f));
            v0.y = to_tf32(fmaxf(acc[nt][1] + sB2[col + 1], 0.f));
            v1.x = to_tf32(fmaxf(acc[nt][2] + sB2[col], 0.f));
            v1.y = to_tf32(fmaxf(acc[nt][3] + sB2[col + 1], 0.f));
            *(float2*)(sA + row0 * A_STRIDE + 64 + col) = v0;
            *(float2*)(sA + row1 * A_STRIDE + 64 + col) = v1;
        }
        __syncthreads();   // h2 ready, W2T reads done

        // ---- stream W3T into shared slot ----
        {
            const float4* s = (const float4*)g_W3T;
            float4* d = (float4*)sW23;
            for (int i = tid; i < 64 * W23_STRIDE / 4; i += NTHREADS) d[i] = s[i];
        }
        __syncthreads();

        // ================= Layer 3: [128x64] @ W3 =================
#pragma unroll
        for (int nt = 0; nt < 4; ++nt)
#pragma unroll
            for (int j = 0; j < 4; ++j) acc[nt][j] = 0.0f;
        {
            const uint32_t* Ar0 = (const uint32_t*)(sA + row0 * A_STRIDE + 64 + t);
            const uint32_t* Ar1 = (const uint32_t*)(sA + row1 * A_STRIDE + 64 + t);
#pragma unroll
            for (int kk = 0; kk < 8; ++kk) {
                uint32_t a[4];
                a[0] = Ar0[kk * 8];
                a[1] = Ar1[kk * 8];
                a[2] = Ar0[kk * 8 + 4];
                a[3] = Ar1[kk * 8 + 4];
#pragma unroll
                for (int nt = 0; nt < 4; ++nt) {
                    const int n = nh * 32 + nt * 8 + g;
                    const uint32_t* Bp = (const uint32_t*)(sW23 + n * W23_STRIDE + kk * 8 + t);
                    mma16n8k8(acc[nt], a, Bp[0], Bp[4]);
                }
            }
        }

        // ---- layer 4 epilogue: out = relu(h3) . W4 + b4 ----
        {
            float pr0 = 0.0f, pr1 = 0.0f;
#pragma unroll
            for (int nt = 0; nt < 4; ++nt) {
                const int col = nh * 32 + nt * 8 + t * 2;
                pr0 = fmaf(fmaxf(acc[nt][0] + sB3[col], 0.f),     sW4[col],     pr0);
                pr0 = fmaf(fmaxf(acc[nt][1] + sB3[col + 1], 0.f), sW4[col + 1], pr0);
                pr1 = fmaf(fmaxf(acc[nt][2] + sB3[col], 0.f),     sW4[col],     pr1);
                pr1 = fmaf(fmaxf(acc[nt][3] + sB3[col + 1], 0.f), sW4[col + 1], pr1);
            }
            pr0 += __shfl_xor_sync(0xffffffffu, pr0, 1);
            pr0 += __shfl_xor_sync(0xffffffffu, pr0, 2);
            pr1 += __shfl_xor_sync(0xffffffffu, pr1, 1);
            pr1 += __shfl_xor_sync(0xffffffffu, pr1, 2);
            if (t == 0) {
                sPart[nh * 128 + row0] = pr0;
                sPart[nh * 128 + row1] = pr1;
            }
        }
        __syncthreads();
        if (tid < 128) out[p0 + tid] = sPart[tid] + sPart[128 + tid] + b4v;
        __syncthreads();
    }
}

// ---------------------------------------------------------------------------
// Launch
// ---------------------------------------------------------------------------
extern "C" void kernel_launch(void* const* d_in, const int* in_sizes, int n_in,
                              void* d_out, int out_size) {
    const float* features = (const float*)d_in[0];
    const float* points   = (const float*)d_in[1];
    const float* kmat     = (const float*)d_in[2];
    const float* rtm      = (const float*)d_in[3];
    const float* Bg       = (const float*)d_in[4];
    const float* W1 = (const float*)d_in[5];
    const float* b1 = (const float*)d_in[6];
    const float* W2 = (const float*)d_in[7];
    const float* b2 = (const float*)d_in[8];
    const float* W3 = (const float*)d_in[9];
    const float* b3 = (const float*)d_in[10];
    const float* W4 = (const float*)d_in[11];
    const float* b4 = (const float*)d_in[12];

    dim3 tb(32, 32);
    dim3 tg(3136 / 32, CHN / 32, BATCH);
    transpose_kernel<<<tg, tb>>>(features);
    prep_weights_kernel<<<1, 256>>>(W1, W2, W3);

    cudaFuncSetAttribute(decoder_kernel,
                         cudaFuncAttributeMaxDynamicSharedMemorySize, SMEM_TOTAL);
    decoder_kernel<<<GRID_CTAS, NTHREADS, SMEM_TOTAL>>>(
        points, kmat, rtm, Bg, b1, b2, b3, W4, b4, (float*)d_out);
}

// round 5
// speedup vs baseline: 4.1808x; 1.1392x over previous
#include <cuda_runtime.h>
#include <math.h>
#include <stdint.h>

#define BATCH 8
#define CHN 128
#define HH 56
#define WW 56
#define TILE_PTS 128
#define NTHREADS 512
#define NTILES 4096
#define GRID_CTAS 148

#define A_STRIDE 260     // 65 x 16B rows: %8==1 -> conflict-free LDSM
#define W1_STRIDE 260

// float-index offsets in dynamic smem
#define FOFF_A     0                          // 128 x 260
#define FOFF_W1    (128 * A_STRIDE)           // 64 x 260
#define FOFF_MISC  (FOFF_W1 + 64 * W1_STRIDE)
#define MI_B1   0
#define MI_B2   64
#define MI_B3   128
#define MI_W4   192
#define MI_BG   256      // 192 floats
#define MI_FX   448
#define MI_FY   576
#define MI_VA   704
#define MI_X0   832
#define MI_Y0   960
#define MI_PART 1088     // 256 floats
#define SMEM_TOTAL ((FOFF_MISC + 1344) * 4)   // 205,056 bytes

// ---------------- globals ----------------
__device__ float g_tf[BATCH * HH * WW * CHN];   // (B,H,W,C) features
__device__ float g_W1T[64 * W1_STRIDE];         // n-major padded tf32 image
__device__ float g_W2Tc[64 * 64];               // compact n-major tf32
__device__ float g_W3Tc[64 * 64];

__device__ __forceinline__ float to_tf32(float x) {
    uint32_t r;
    asm("cvt.rna.tf32.f32 %0, %1;" : "=r"(r) : "f"(x));
    return __uint_as_float(r);
}
__device__ __forceinline__ uint32_t smem_u32(const void* p) {
    uint32_t a;
    asm("{ .reg .u64 t; cvta.to.shared.u64 t, %1; cvt.u32.u64 %0, t; }" : "=r"(a) : "l"(p));
    return a;
}
__device__ __forceinline__ void ldsm4(uint32_t* r, uint32_t addr) {
    asm volatile("ldmatrix.sync.aligned.m8n8.x4.shared.b16 {%0,%1,%2,%3}, [%4];"
                 : "=r"(r[0]), "=r"(r[1]), "=r"(r[2]), "=r"(r[3]) : "r"(addr));
}
__device__ __forceinline__ void mma16n8k8(float* d, const uint32_t* a, uint32_t b0, uint32_t b1) {
    asm volatile(
        "mma.sync.aligned.m16n8k8.row.col.f32.tf32.tf32.f32 "
        "{%0,%1,%2,%3}, {%4,%5,%6,%7}, {%8,%9}, {%0,%1,%2,%3};"
        : "+f"(d[0]), "+f"(d[1]), "+f"(d[2]), "+f"(d[3])
        : "r"(a[0]), "r"(a[1]), "r"(a[2]), "r"(a[3]), "r"(b0), "r"(b1));
}

// ---------------------------------------------------------------------------
// Kernel 1: transpose features + prep weight images (merged)
// ---------------------------------------------------------------------------
__global__ void transpose_kernel(const float* __restrict__ f,
                                 const float* __restrict__ W1,
                                 const float* __restrict__ W2,
                                 const float* __restrict__ W3) {
    __shared__ float tile[32][33];
    const int b  = blockIdx.z;
    const int c0 = blockIdx.y << 5;
    const int s0 = blockIdx.x << 5;
    const int tx = threadIdx.x, ty = threadIdx.y;
    tile[ty][tx] = f[(size_t)(b * CHN + c0 + ty) * 3136 + (s0 + tx)];
    __syncthreads();
    g_tf[(size_t)(b * 3136 + s0 + ty) * CHN + (c0 + tx)] = tile[tx][ty];

    // 8 blocks (x==0,y==0, z=0..7) also prep weight images
    if (blockIdx.x == 0 && blockIdx.y == 0) {
        const int t = ty * 32 + tx;                 // 0..1023
        const int base = b * 1024 + t;              // 0..8191
        for (int i = base; i < 64 * 256; i += 8192) {
            int n = i & 63, k = i >> 6;
            g_W1T[n * W1_STRIDE + k] = to_tf32(W1[k * 64 + n]);
        }
        for (int i = base; i < 64 * 64; i += 8192) {
            int n = i & 63, k = i >> 6;
            g_W2Tc[n * 64 + k] = to_tf32(W2[k * 64 + n]);
            g_W3Tc[n * 64 + k] = to_tf32(W3[k * 64 + n]);
        }
    }
}

// ---------------------------------------------------------------------------
// Kernel 2: persistent fused decoder (mma.sync tf32 + ldmatrix)
// ---------------------------------------------------------------------------
__global__ __launch_bounds__(NTHREADS, 1)
void decoder_kernel(const float* __restrict__ points,
                    const float* __restrict__ kmat,
                    const float* __restrict__ rtm,
                    const float* __restrict__ Bg,
                    const float* __restrict__ b1,
                    const float* __restrict__ b2,
                    const float* __restrict__ b3,
                    const float* __restrict__ W4,
                    const float* __restrict__ b4,
                    float* __restrict__ out) {
    extern __shared__ float sm[];
    float* sA   = sm + FOFF_A;
    float* sW1  = sm + FOFF_W1;
    float* sMi  = sm + FOFF_MISC;
    float* sB1 = sMi + MI_B1;
    float* sB2 = sMi + MI_B2;
    float* sB3 = sMi + MI_B3;
    float* sW4 = sMi + MI_W4;
    float* sBg = sMi + MI_BG;
    float* sFx = sMi + MI_FX;
    float* sFy = sMi + MI_FY;
    float* sVa = sMi + MI_VA;
    int*   sX0 = (int*)(sMi + MI_X0);
    int*   sY0 = (int*)(sMi + MI_Y0);
    float* sPart = sMi + MI_PART;

    const int tid  = threadIdx.x;
    const int wid  = tid >> 5;
    const int lane = tid & 31;
    const int pid  = tid & 127;

    // mma role decomposition
    const int mt = wid >> 1;          // m-tile 0..7 (rows mt*16 .. +16)
    const int nh = wid & 1;           // col half: cols nh*32 .. +32
    const int g  = lane >> 2;         // 0..7
    const int t  = lane & 3;          // 0..3
    const int row0 = mt * 16 + g;
    const int row1 = row0 + 8;

    const uint32_t sAu  = smem_u32(sA);
    const uint32_t sW1u = smem_u32(sW1);

    // ldmatrix per-lane addresses
    const int arow = mt * 16 + (lane & 15);
    const int acol = (lane >> 4) << 2;                       // 0 or 4
    const uint32_t aBase = sAu + (uint32_t)((arow * A_STRIDE + acol) << 2);
    const int nrow = nh * 32 + ((lane & 16) >> 1) + (lane & 7);
    const int ncol = (lane & 8) ? 4 : 0;
    const uint32_t b1Base  = sW1u + (uint32_t)((nrow * W1_STRIDE + ncol) << 2);
    const uint32_t b1Base2 = b1Base + (uint32_t)(16 * W1_STRIDE * 4);
    const uint32_t bW2Base  = sAu + (uint32_t)((nrow * A_STRIDE + 128 + ncol) << 2);
    const uint32_t bW2Base2 = bW2Base + (uint32_t)(16 * A_STRIDE * 4);
    const uint32_t bW3Base  = bW2Base + 64 * 4;   // cols 192..256
    const uint32_t bW3Base2 = bW3Base + (uint32_t)(16 * A_STRIDE * 4);

    // ---- one-time init ----
    {
        const float4* s = (const float4*)g_W1T;
        float4* d = (float4*)sW1;
        for (int i = tid; i < 64 * W1_STRIDE / 4; i += NTHREADS) d[i] = s[i];
    }
    if (tid < 64) {
        sB1[tid] = b1[tid]; sB2[tid] = b2[tid]; sB3[tid] = b3[tid];
        sW4[tid] = W4[tid];
    }
    if (tid < 96) ((float2*)sBg)[tid] = ((const float2*)Bg)[tid];
    const float b4v = b4[0];
    __syncthreads();

    for (int tile = blockIdx.x; tile < NTILES; tile += GRID_CTAS) {
        const int p0 = tile * TILE_PTS;
        const int b  = p0 >> 16;

        // ---- projection (threads 0..127) ----
        const float* pt = points + (size_t)(p0 + pid) * 3;
        const float px = pt[0], py = pt[1], pz = pt[2];
        if (tid < 128) {
            const float* R = rtm + b * 12;
            const float* K = kmat + b * 9;
            const float cx = fmaf(R[0], px, fmaf(R[1], py, fmaf(R[2],  pz, R[3])));
            const float cy = fmaf(R[4], px, fmaf(R[5], py, fmaf(R[6],  pz, R[7])));
            const float cz = fmaf(R[8], px, fmaf(R[9], py, fmaf(R[10], pz, R[11])));
            const float ix = fmaf(K[0], cx, fmaf(K[1], cy, K[2] * cz));
            const float iy = fmaf(K[3], cx, fmaf(K[4], cy, K[5] * cz));
            const float iz = fmaf(K[6], cx, fmaf(K[7], cy, K[8] * cz));
            const bool  pos = (iz > 0.0f);
            const float zz = iz + 1e-8f;
            const float u = __fdividef(ix, zz), v = __fdividef(iy, zz);
            const float xf = floorf(u), yf = floorf(v);
            float fx = u - xf, fy = v - yf;
            int x0 = (int)xf, y0 = (int)yf;
            if (!pos) { x0 = -100000; y0 = -100000; fx = 0.0f; fy = 0.0f; }
            sFx[pid] = fx; sFy[pid] = fy; sVa[pid] = pos ? 1.0f : 0.0f;
            sX0[pid] = x0; sY0[pid] = y0;
        }
        __syncthreads();

        // ---- warp-cooperative bilinear gather -> A cols [0,128) ----
        {
            const int q0 = wid << 3;      // 16 warps x 8 points
            const float* baseb = g_tf + (size_t)b * 3136 * CHN + lane * 4;
#pragma unroll 2
            for (int i = 0; i < 8; ++i) {
                const int q = q0 + i;
                const float gfx = sFx[q], gfy = sFy[q], gv = sVa[q];
                const int gx = sX0[q], gy = sY0[q];
                const float ax = 1.0f - gfx, ay = 1.0f - gfy;
                const float w00 = ax * ay * gv;
                const float w10 = gfx * ay * gv;
                const float w01 = ax * gfy * gv;
                const float w11 = gfx * gfy * gv;
                const bool x0in = (gx >= 0) && (gx < WW);
                const bool x1in = (gx >= -1) && (gx < WW - 1);
                const bool y0in = (gy >= 0) && (gy < HH);
                const bool y1in = (gy >= -1) && (gy < HH - 1);
                const int rowoff = (gy * WW + gx) * CHN;
                float4 acc = make_float4(0.f, 0.f, 0.f, 0.f);
                if (x0in && y0in) {
                    float4 v4 = *(const float4*)(baseb + rowoff);
                    acc.x = fmaf(w00, v4.x, acc.x); acc.y = fmaf(w00, v4.y, acc.y);
                    acc.z = fmaf(w00, v4.z, acc.z); acc.w = fmaf(w00, v4.w, acc.w);
                }
                if (x1in && y0in) {
                    float4 v4 = *(const float4*)(baseb + rowoff + CHN);
                    acc.x = fmaf(w10, v4.x, acc.x); acc.y = fmaf(w10, v4.y, acc.y);
                    acc.z = fmaf(w10, v4.z, acc.z); acc.w = fmaf(w10, v4.w, acc.w);
                }
                if (x0in && y1in) {
                    float4 v4 = *(const float4*)(baseb + rowoff + WW * CHN);
                    acc.x = fmaf(w01, v4.x, acc.x); acc.y = fmaf(w01, v4.y, acc.y);
                    acc.z = fmaf(w01, v4.z, acc.z); acc.w = fmaf(w01, v4.w, acc.w);
                }
                if (x1in && y1in) {
                    float4 v4 = *(const float4*)(baseb + rowoff + (WW + 1) * CHN);
                    acc.x = fmaf(w11, v4.x, acc.x); acc.y = fmaf(w11, v4.y, acc.y);
                    acc.z = fmaf(w11, v4.z, acc.z); acc.w = fmaf(w11, v4.w, acc.w);
                }
                acc.x = to_tf32(acc.x); acc.y = to_tf32(acc.y);
                acc.z = to_tf32(acc.z); acc.w = to_tf32(acc.w);
                *(float4*)(sA + q * A_STRIDE + lane * 4) = acc;
            }
        }

        // ---- Fourier features -> A cols [128,256) ----
        {
            const float TWOPI = 6.283185307179586f;
            const int mg = tid >> 7;              // 0..3, 16 m's each
            float* arow2 = sA + pid * A_STRIDE;
#pragma unroll 4
            for (int j = 0; j < 16; ++j) {
                const int m = mg * 16 + j;
                float xp = TWOPI * fmaf(px, sBg[m * 3],
                                 fmaf(py, sBg[m * 3 + 1], pz * sBg[m * 3 + 2]));
                arow2[128 + m] = to_tf32(__sinf(xp));
                arow2[192 + m] = to_tf32(__cosf(xp));
            }
        }
        __syncthreads();   // A fully built

        // ================= Layer 1: [128x256] @ W1 -> [128x64] =================
        float acc[4][4];
#pragma unroll
        for (int nt = 0; nt < 4; ++nt)
#pragma unroll
            for (int j = 0; j < 4; ++j) acc[nt][j] = 0.0f;
#pragma unroll 4
        for (int kk = 0; kk < 32; ++kk) {
            uint32_t a[4], B[8];
            ldsm4(a, aBase + kk * 32);
            ldsm4(B,     b1Base  + kk * 32);
            ldsm4(B + 4, b1Base2 + kk * 32);
            mma16n8k8(acc[0], a, B[0], B[1]);
            mma16n8k8(acc[1], a, B[2], B[3]);
            mma16n8k8(acc[2], a, B[4], B[5]);
            mma16n8k8(acc[3], a, B[6], B[7]);
        }
        __syncthreads();   // all L1 A-reads done; cols [128,256) now dead

        // ---- stream W2/W3 into A cols [128,192) / [192,256), rows 0..63 ----
        {
            const float4* s2 = (const float4*)g_W2Tc;
            const float4* s3 = (const float4*)g_W3Tc;
#pragma unroll 2
            for (int i = tid; i < 1024; i += NTHREADS) {
                const int n = i >> 4, c4 = (i & 15) << 2;
                *(float4*)(sA + n * A_STRIDE + 128 + c4) = s2[i];
                *(float4*)(sA + n * A_STRIDE + 192 + c4) = s3[i];
            }
        }
        // relu(acc + b1) -> A cols [0,64)
#pragma unroll
        for (int nt = 0; nt < 4; ++nt) {
            const int col = nh * 32 + nt * 8 + t * 2;
            float2 v0, v1;
            v0.x = to_tf32(fmaxf(acc[nt][0] + sB1[col], 0.f));
            v0.y = to_tf32(fmaxf(acc[nt][1] + sB1[col + 1], 0.f));
            v1.x = to_tf32(fmaxf(acc[nt][2] + sB1[col], 0.f));
            v1.y = to_tf32(fmaxf(acc[nt][3] + sB1[col + 1], 0.f));
            *(float2*)(sA + row0 * A_STRIDE + col) = v0;
            *(float2*)(sA + row1 * A_STRIDE + col) = v1;
        }
        __syncthreads();   // h1 + W2/W3 ready

        // ================= Layer 2: h1[128x64] @ W2 =================
#pragma unroll
        for (int nt = 0; nt < 4; ++nt)
#pragma unroll
            for (int j = 0; j < 4; ++j) acc[nt][j] = 0.0f;
#pragma unroll
        for (int kk = 0; kk < 8; ++kk) {
            uint32_t a[4], B[8];
            ldsm4(a, aBase + kk * 32);
            ldsm4(B,     bW2Base  + kk * 32);
            ldsm4(B + 4, bW2Base2 + kk * 32);
            mma16n8k8(acc[0], a, B[0], B[1]);
            mma16n8k8(acc[1], a, B[2], B[3]);
            mma16n8k8(acc[2], a, B[4], B[5]);
            mma16n8k8(acc[3], a, B[6], B[7]);
        }
        // relu(acc + b2) -> A cols [64,128)   (disjoint from all L2 reads)
#pragma unroll
        for (int nt = 0; nt < 4; ++nt) {
            const int col = nh * 32 + nt * 8 + t * 2;
            float2 v0, v1;
            v0.x = to_tf32(fmaxf(acc[nt][0] + sB2[col], 0.f));
            v0.y = to_tf32(fmaxf(acc[nt][1] + sB2[col + 1], 0.f));
            v1.x = to_tf32(fmaxf(acc[nt][2] + sB2[col], 0.f));
            v1.y = to_tf32(fmaxf(acc[nt][3] + sB2[col + 1], 0.f));
            *(float2*)(sA + row0 * A_STRIDE + 64 + col) = v0;
            *(float2*)(sA + row1 * A_STRIDE + 64 + col) = v1;
        }
        __syncthreads();   // h2 ready

        // ================= Layer 3: h2[128x64] @ W3 =================
#pragma unroll
        for (int nt = 0; nt < 4; ++nt)
#pragma unroll
            for (int j = 0; j < 4; ++j) acc[nt][j] = 0.0f;
#pragma unroll
        for (int kk = 0; kk < 8; ++kk) {
            uint32_t a[4], B[8];
            ldsm4(a, aBase + 64 * 4 + kk * 32);
            ldsm4(B,     bW3Base  + kk * 32);
            ldsm4(B + 4, bW3Base2 + kk * 32);
            mma16n8k8(acc[0], a, B[0], B[1]);
            mma16n8k8(acc[1], a, B[2], B[3]);
            mma16n8k8(acc[2], a, B[4], B[5]);
            mma16n8k8(acc[3], a, B[6], B[7]);
        }

        // ---- layer 4 epilogue: out = relu(h3) . W4 + b4 ----
        {
            float pr0 = 0.0f, pr1 = 0.0f;
#pragma unroll
            for (int nt = 0; nt < 4; ++nt) {
                const int col = nh * 32 + nt * 8 + t * 2;
                pr0 = fmaf(fmaxf(acc[nt][0] + sB3[col], 0.f),     sW4[col],     pr0);
                pr0 = fmaf(fmaxf(acc[nt][1] + sB3[col + 1], 0.f), sW4[col + 1], pr0);
                pr1 = fmaf(fmaxf(acc[nt][2] + sB3[col], 0.f),     sW4[col],     pr1);
                pr1 = fmaf(fmaxf(acc[nt][3] + sB3[col + 1], 0.f), sW4[col + 1], pr1);
            }
            pr0 += __shfl_xor_sync(0xffffffffu, pr0, 1);
            pr0 += __shfl_xor_sync(0xffffffffu, pr0, 2);
            pr1 += __shfl_xor_sync(0xffffffffu, pr1, 1);
            pr1 += __shfl_xor_sync(0xffffffffu, pr1, 2);
            if (t == 0) {
                sPart[nh * 128 + row0] = pr0;
                sPart[nh * 128 + row1] = pr1;
            }
        }
        __syncthreads();   // sPart ready; all L3 A-reads done
        if (tid < 128) out[p0 + tid] = sPart[tid] + sPart[128 + tid] + b4v;
    }
}

// ---------------------------------------------------------------------------
// Launch
// ---------------------------------------------------------------------------
extern "C" void kernel_launch(void* const* d_in, const int* in_sizes, int n_in,
                              void* d_out, int out_size) {
    const float* features = (const float*)d_in[0];
    const float* points   = (const float*)d_in[1];
    const float* kmat     = (const float*)d_in[2];
    const float* rtm      = (const float*)d_in[3];
    const float* Bg       = (const float*)d_in[4];
    const float* W1 = (const float*)d_in[5];
    const float* b1 = (const float*)d_in[6];
    const float* W2 = (const float*)d_in[7];
    const float* b2 = (const float*)d_in[8];
    const float* W3 = (const float*)d_in[9];
    const float* b3 = (const float*)d_in[10];
    const float* W4 = (const float*)d_in[11];
    const float* b4 = (const float*)d_in[12];

    dim3 tb(32, 32);
    dim3 tg(3136 / 32, CHN / 32, BATCH);
    transpose_kernel<<<tg, tb>>>(features, W1, W2, W3);

    cudaFuncSetAttribute(decoder_kernel,
                         cudaFuncAttributeMaxDynamicSharedMemorySize, SMEM_TOTAL);
    decoder_kernel<<<GRID_CTAS, NTHREADS, SMEM_TOTAL>>>(
        points, kmat, rtm, Bg, b1, b2, b3, W4, b4, (float*)d_out);
}

// round 6
// speedup vs baseline: 4.2177x; 1.0088x over previous
#include <cuda_runtime.h>
#include <math.h>
#include <stdint.h>

#define BATCH 8
#define CHN 128
#define HH 56
#define WW 56
#define TILE_PTS 128
#define NTHREADS 256
#define NTILES 4096
#define GRID_CTAS 148

#define A_STRIDE 260     // 65 x 16B rows: %8==1 -> conflict-free LDSM
#define W1_STRIDE 260
#define WST 68           // staging stride for W2/W3 (%8==4, conflict-free)

// float-index offsets in dynamic smem
#define FOFF_A     0                          // 128 x 260 = 33280
#define FOFF_W1    (128 * A_STRIDE)           // 64 x 260 = 16640
#define FOFF_MISC  (FOFF_W1 + 64 * W1_STRIDE)
#define MI_B1   0
#define MI_B2   64
#define MI_B3   128
#define MI_W4   192
#define MI_BG   256      // 192 floats
#define MI_FX   448
#define MI_FY   576
#define MI_VA   704
#define MI_X0   832
#define MI_Y0   960
#define MI_PX   1088
#define MI_PY   1216
#define MI_PZ   1344
#define MI_PART 1472     // 256 floats
#define SMEM_TOTAL ((FOFF_MISC + 1792) * 4)   // 206,848 bytes

// ---------------- globals ----------------
__device__ float g_tf[BATCH * HH * WW * CHN];   // (B,H,W,C) features
__device__ float g_W1T[64 * W1_STRIDE];         // n-major padded tf32 image
__device__ float g_W2Tc[64 * 64];               // compact n-major tf32
__device__ float g_W3Tc[64 * 64];

__device__ __forceinline__ float to_tf32(float x) {
    uint32_t r;
    asm("cvt.rna.tf32.f32 %0, %1;" : "=r"(r) : "f"(x));
    return __uint_as_float(r);
}
__device__ __forceinline__ uint32_t smem_u32(const void* p) {
    uint32_t a;
    asm("{ .reg .u64 t; cvta.to.shared.u64 t, %1; cvt.u32.u64 %0, t; }" : "=r"(a) : "l"(p));
    return a;
}
__device__ __forceinline__ void ldsm4(uint32_t* r, uint32_t addr) {
    asm volatile("ldmatrix.sync.aligned.m8n8.x4.shared.b16 {%0,%1,%2,%3}, [%4];"
                 : "=r"(r[0]), "=r"(r[1]), "=r"(r[2]), "=r"(r[3]) : "r"(addr));
}
__device__ __forceinline__ void mma16n8k8(float* d, const uint32_t* a, uint32_t b0, uint32_t b1) {
    asm volatile(
        "mma.sync.aligned.m16n8k8.row.col.f32.tf32.tf32.f32 "
        "{%0,%1,%2,%3}, {%4,%5,%6,%7}, {%8,%9}, {%0,%1,%2,%3};"
        : "+f"(d[0]), "+f"(d[1]), "+f"(d[2]), "+f"(d[3])
        : "r"(a[0]), "r"(a[1]), "r"(a[2]), "r"(a[3]), "r"(b0), "r"(b1));
}

// ---------------------------------------------------------------------------
// Kernel 1: transpose features + prep weight images (merged)
// ---------------------------------------------------------------------------
__global__ void transpose_kernel(const float* __restrict__ f,
                                 const float* __restrict__ W1,
                                 const float* __restrict__ W2,
                                 const float* __restrict__ W3) {
    __shared__ float tile[32][33];
    const int b  = blockIdx.z;
    const int c0 = blockIdx.y << 5;
    const int s0 = blockIdx.x << 5;
    const int tx = threadIdx.x, ty = threadIdx.y;
    tile[ty][tx] = f[(size_t)(b * CHN + c0 + ty) * 3136 + (s0 + tx)];
    __syncthreads();
    g_tf[(size_t)(b * 3136 + s0 + ty) * CHN + (c0 + tx)] = tile[tx][ty];

    if (blockIdx.x == 0 && blockIdx.y == 0) {
        const int t = ty * 32 + tx;
        const int base = b * 1024 + t;
        for (int i = base; i < 64 * 256; i += 8192) {
            int n = i & 63, k = i >> 6;
            g_W1T[n * W1_STRIDE + k] = to_tf32(W1[k * 64 + n]);
        }
        for (int i = base; i < 64 * 64; i += 8192) {
            int n = i & 63, k = i >> 6;
            g_W2Tc[n * 64 + k] = to_tf32(W2[k * 64 + n]);
            g_W3Tc[n * 64 + k] = to_tf32(W3[k * 64 + n]);
        }
    }
}

// ---------------------------------------------------------------------------
// Kernel 2: persistent fused decoder
//   8 warps, warp = (mslot 0..3) x (nslot 0..1): Mw=32, Nw=32 per warp
//   W2/W3 B-fragments register-resident across all tiles
// ---------------------------------------------------------------------------
__global__ __launch_bounds__(NTHREADS, 1)
void decoder_kernel(const float* __restrict__ points,
                    const float* __restrict__ kmat,
                    const float* __restrict__ rtm,
                    const float* __restrict__ Bg,
                    const float* __restrict__ b1,
                    const float* __restrict__ b2,
                    const float* __restrict__ b3,
                    const float* __restrict__ W4,
                    const float* __restrict__ b4,
                    float* __restrict__ out) {
    extern __shared__ float sm[];
    float* sA  = sm + FOFF_A;
    float* sW1 = sm + FOFF_W1;
    float* sMi = sm + FOFF_MISC;
    float* sB1 = sMi + MI_B1;
    float* sB2 = sMi + MI_B2;
    float* sB3 = sMi + MI_B3;
    float* sW4 = sMi + MI_W4;
    float* sBg = sMi + MI_BG;
    float* sFx = sMi + MI_FX;
    float* sFy = sMi + MI_FY;
    float* sVa = sMi + MI_VA;
    int*   sX0 = (int*)(sMi + MI_X0);
    int*   sY0 = (int*)(sMi + MI_Y0);
    float* sPx = sMi + MI_PX;
    float* sPy = sMi + MI_PY;
    float* sPz = sMi + MI_PZ;
    float* sPart = sMi + MI_PART;

    const int tid  = threadIdx.x;
    const int wid  = tid >> 5;
    const int lane = tid & 31;

    // warp tile roles
    const int mslot = wid >> 1;       // 0..3: rows mslot*32 .. +32
    const int nslot = wid & 1;        // 0..1: cols nslot*32 .. +32
    const int g  = lane >> 2;
    const int t  = lane & 3;

    const uint32_t sAu  = smem_u32(sA);
    const uint32_t sW1u = smem_u32(sW1);

    // A-frag ldsm addresses (two m16 tiles)
    const int arow = mslot * 32 + (lane & 15);
    const int acol = (lane >> 4) << 2;
    const uint32_t aBase0 = sAu + (uint32_t)(((arow)      * A_STRIDE + acol) << 2);
    const uint32_t aBase1 = sAu + (uint32_t)(((arow + 16) * A_STRIDE + acol) << 2);
    // W1 B-frag addresses (two n16 groups)
    const int nrow = nslot * 32 + ((lane & 16) >> 1) + (lane & 7);
    const int ncol = (lane & 8) ? 4 : 0;
    const uint32_t b1Base0 = sW1u + (uint32_t)((nrow * W1_STRIDE + ncol) << 2);
    const uint32_t b1Base1 = b1Base0 + (uint32_t)(16 * W1_STRIDE * 4);

    // ---- one-time init ----
    {
        const float4* s = (const float4*)g_W1T;
        float4* d = (float4*)sW1;
        for (int i = tid; i < 64 * W1_STRIDE / 4; i += NTHREADS) d[i] = s[i];
    }
    if (tid < 64) {
        sB1[tid] = b1[tid]; sB2[tid] = b2[tid]; sB3[tid] = b3[tid];
        sW4[tid] = W4[tid];
    }
    if (tid < 96) ((float2*)sBg)[tid] = ((const float2*)Bg)[tid];
    const float b4v = b4[0];

    // stage W2/W3 into sA (stride WST) and hoist B-fragments to registers
    for (int i = tid; i < 64 * 64; i += NTHREADS) {
        int n = i >> 6, k = i & 63;
        sA[n * WST + k]            = g_W2Tc[i];
        sA[64 * WST + n * WST + k] = g_W3Tc[i];
    }
    __syncthreads();
    uint32_t B2f[64], B3f[64];
    {
        const int wrow = nslot * 32 + ((lane & 16) >> 1) + (lane & 7);
        const uint32_t wcol = (lane & 8) ? 4u : 0u;
        const uint32_t wBase0 = sAu + (uint32_t)(((wrow * WST + wcol)) << 2);
        const uint32_t wBase1 = wBase0 + (uint32_t)(16 * WST * 4);
        const uint32_t w3off  = (uint32_t)(64 * WST * 4);
#pragma unroll
        for (int kk = 0; kk < 8; ++kk) {
            ldsm4(B2f + kk * 8,     wBase0 + kk * 32);
            ldsm4(B2f + kk * 8 + 4, wBase1 + kk * 32);
            ldsm4(B3f + kk * 8,     wBase0 + w3off + kk * 32);
            ldsm4(B3f + kk * 8 + 4, wBase1 + w3off + kk * 32);
        }
    }
    __syncthreads();

    for (int tile = blockIdx.x; tile < NTILES; tile += GRID_CTAS) {
        const int p0 = tile * TILE_PTS;
        const int b  = p0 >> 16;

        // ---- projection (threads 0..127, one point each) ----
        if (tid < 128) {
            const float* pt = points + (size_t)(p0 + tid) * 3;
            const float px = pt[0], py = pt[1], pz = pt[2];
            const float* R = rtm + b * 12;
            const float* K = kmat + b * 9;
            const float cx = fmaf(R[0], px, fmaf(R[1], py, fmaf(R[2],  pz, R[3])));
            const float cy = fmaf(R[4], px, fmaf(R[5], py, fmaf(R[6],  pz, R[7])));
            const float cz = fmaf(R[8], px, fmaf(R[9], py, fmaf(R[10], pz, R[11])));
            const float ix = fmaf(K[0], cx, fmaf(K[1], cy, K[2] * cz));
            const float iy = fmaf(K[3], cx, fmaf(K[4], cy, K[5] * cz));
            const float iz = fmaf(K[6], cx, fmaf(K[7], cy, K[8] * cz));
            const bool  pos = (iz > 0.0f);
            const float zz = iz + 1e-8f;
            const float u = __fdividef(ix, zz), v = __fdividef(iy, zz);
            const float xf = floorf(u), yf = floorf(v);
            float fx = u - xf, fy = v - yf;
            int x0 = (int)xf, y0 = (int)yf;
            if (!pos) { x0 = -100000; y0 = -100000; fx = 0.0f; fy = 0.0f; }
            sFx[tid] = fx; sFy[tid] = fy; sVa[tid] = pos ? 1.0f : 0.0f;
            sX0[tid] = x0; sY0[tid] = y0;
            sPx[tid] = px; sPy[tid] = py; sPz[tid] = pz;
        }
        __syncthreads();

        // ---- warp-cooperative bilinear gather: 8 warps x 16 points ----
        {
            const int q0 = wid << 4;
            const float* baseb = g_tf + (size_t)b * 3136 * CHN + lane * 4;
#pragma unroll 2
            for (int i = 0; i < 16; ++i) {
                const int q = q0 + i;
                const float gfx = sFx[q], gfy = sFy[q], gv = sVa[q];
                const int gx = sX0[q], gy = sY0[q];
                const float ax = 1.0f - gfx, ay = 1.0f - gfy;
                const float w00 = ax * ay * gv;
                const float w10 = gfx * ay * gv;
                const float w01 = ax * gfy * gv;
                const float w11 = gfx * gfy * gv;
                const bool x0in = (gx >= 0) && (gx < WW);
                const bool x1in = (gx >= -1) && (gx < WW - 1);
                const bool y0in = (gy >= 0) && (gy < HH);
                const bool y1in = (gy >= -1) && (gy < HH - 1);
                const int rowoff = (gy * WW + gx) * CHN;
                float4 acc = make_float4(0.f, 0.f, 0.f, 0.f);
                if (x0in && y0in) {
                    float4 v4 = *(const float4*)(baseb + rowoff);
                    acc.x = fmaf(w00, v4.x, acc.x); acc.y = fmaf(w00, v4.y, acc.y);
                    acc.z = fmaf(w00, v4.z, acc.z); acc.w = fmaf(w00, v4.w, acc.w);
                }
                if (x1in && y0in) {
                    float4 v4 = *(const float4*)(baseb + rowoff + CHN);
                    acc.x = fmaf(w10, v4.x, acc.x); acc.y = fmaf(w10, v4.y, acc.y);
                    acc.z = fmaf(w10, v4.z, acc.z); acc.w = fmaf(w10, v4.w, acc.w);
                }
                if (x0in && y1in) {
                    float4 v4 = *(const float4*)(baseb + rowoff + WW * CHN);
                    acc.x = fmaf(w01, v4.x, acc.x); acc.y = fmaf(w01, v4.y, acc.y);
                    acc.z = fmaf(w01, v4.z, acc.z); acc.w = fmaf(w01, v4.w, acc.w);
                }
                if (x1in && y1in) {
                    float4 v4 = *(const float4*)(baseb + rowoff + (WW + 1) * CHN);
                    acc.x = fmaf(w11, v4.x, acc.x); acc.y = fmaf(w11, v4.y, acc.y);
                    acc.z = fmaf(w11, v4.z, acc.z); acc.w = fmaf(w11, v4.w, acc.w);
                }
                acc.x = to_tf32(acc.x); acc.y = to_tf32(acc.y);
                acc.z = to_tf32(acc.z); acc.w = to_tf32(acc.w);
                *(float4*)(sA + q * A_STRIDE + lane * 4) = acc;
            }
        }

        // ---- Fourier: lanes write consecutive columns (conflict-free STS) ----
        {
            const float TWOPI = 6.283185307179586f;
            const int q0 = wid << 4;
#pragma unroll 2
            for (int i = 0; i < 16; ++i) {
                const int q = q0 + i;
                const float qx = sPx[q], qy = sPy[q], qz = sPz[q];
                const int m0 = lane, m1 = lane + 32;
                const float xp0 = TWOPI * fmaf(qx, sBg[m0 * 3],
                                        fmaf(qy, sBg[m0 * 3 + 1], qz * sBg[m0 * 3 + 2]));
                const float xp1 = TWOPI * fmaf(qx, sBg[m1 * 3],
                                        fmaf(qy, sBg[m1 * 3 + 1], qz * sBg[m1 * 3 + 2]));
                float* row = sA + q * A_STRIDE;
                row[128 + m0] = to_tf32(__sinf(xp0));
                row[128 + m1] = to_tf32(__sinf(xp1));
                row[192 + m0] = to_tf32(__cosf(xp0));
                row[192 + m1] = to_tf32(__cosf(xp1));
            }
        }
        __syncthreads();   // A fully built

        // ================= Layer 1: [128x256] @ W1 -> [128x64] =================
        float acc[2][4][4];
#pragma unroll
        for (int mt = 0; mt < 2; ++mt)
#pragma unroll
            for (int nt = 0; nt < 4; ++nt)
#pragma unroll
                for (int j = 0; j < 4; ++j) acc[mt][nt][j] = 0.0f;
#pragma unroll 4
        for (int kk = 0; kk < 32; ++kk) {
            uint32_t a0[4], a1[4], B[8];
            ldsm4(a0, aBase0 + kk * 32);
            ldsm4(a1, aBase1 + kk * 32);
            ldsm4(B,     b1Base0 + kk * 32);
            ldsm4(B + 4, b1Base1 + kk * 32);
            mma16n8k8(acc[0][0], a0, B[0], B[1]);
            mma16n8k8(acc[0][1], a0, B[2], B[3]);
            mma16n8k8(acc[0][2], a0, B[4], B[5]);
            mma16n8k8(acc[0][3], a0, B[6], B[7]);
            mma16n8k8(acc[1][0], a1, B[0], B[1]);
            mma16n8k8(acc[1][1], a1, B[2], B[3]);
            mma16n8k8(acc[1][2], a1, B[4], B[5]);
            mma16n8k8(acc[1][3], a1, B[6], B[7]);
        }
        __syncthreads();   // all L1 A-reads done

        // relu(acc + b1) -> A cols [0,64)
#pragma unroll
        for (int mt = 0; mt < 2; ++mt) {
            const int r0 = mslot * 32 + mt * 16 + g;
#pragma unroll
            for (int nt = 0; nt < 4; ++nt) {
                const int col = nslot * 32 + nt * 8 + t * 2;
                float2 v0, v1;
                v0.x = to_tf32(fmaxf(acc[mt][nt][0] + sB1[col], 0.f));
                v0.y = to_tf32(fmaxf(acc[mt][nt][1] + sB1[col + 1], 0.f));
                v1.x = to_tf32(fmaxf(acc[mt][nt][2] + sB1[col], 0.f));
                v1.y = to_tf32(fmaxf(acc[mt][nt][3] + sB1[col + 1], 0.f));
                *(float2*)(sA + r0 * A_STRIDE + col) = v0;
                *(float2*)(sA + (r0 + 8) * A_STRIDE + col) = v1;
            }
        }
        __syncthreads();   // h1 ready

        // ================= Layer 2: h1 @ W2 (B in registers) =================
#pragma unroll
        for (int mt = 0; mt < 2; ++mt)
#pragma unroll
            for (int nt = 0; nt < 4; ++nt)
#pragma unroll
                for (int j = 0; j < 4; ++j) acc[mt][nt][j] = 0.0f;
#pragma unroll
        for (int kk = 0; kk < 8; ++kk) {
            uint32_t a0[4], a1[4];
            ldsm4(a0, aBase0 + kk * 32);
            ldsm4(a1, aBase1 + kk * 32);
#pragma unroll
            for (int nt = 0; nt < 4; ++nt) {
                mma16n8k8(acc[0][nt], a0, B2f[kk * 8 + nt * 2], B2f[kk * 8 + nt * 2 + 1]);
                mma16n8k8(acc[1][nt], a1, B2f[kk * 8 + nt * 2], B2f[kk * 8 + nt * 2 + 1]);
            }
        }
        // relu(acc + b2) -> A cols [64,128)  (disjoint from L2 reads)
#pragma unroll
        for (int mt = 0; mt < 2; ++mt) {
            const int r0 = mslot * 32 + mt * 16 + g;
#pragma unroll
            for (int nt = 0; nt < 4; ++nt) {
                const int col = nslot * 32 + nt * 8 + t * 2;
                float2 v0, v1;
                v0.x = to_tf32(fmaxf(acc[mt][nt][0] + sB2[col], 0.f));
                v0.y = to_tf32(fmaxf(acc[mt][nt][1] + sB2[col + 1], 0.f));
                v1.x = to_tf32(fmaxf(acc[mt][nt][2] + sB2[col], 0.f));
                v1.y = to_tf32(fmaxf(acc[mt][nt][3] + sB2[col + 1], 0.f));
                *(float2*)(sA + r0 * A_STRIDE + 64 + col) = v0;
                *(float2*)(sA + (r0 + 8) * A_STRIDE + 64 + col) = v1;
            }
        }
        __syncthreads();   // h2 ready

        // ================= Layer 3: h2 @ W3 (B in registers) =================
#pragma unroll
        for (int mt = 0; mt < 2; ++mt)
#pragma unroll
            for (int nt = 0; nt < 4; ++nt)
#pragma unroll
                for (int j = 0; j < 4; ++j) acc[mt][nt][j] = 0.0f;
#pragma unroll
        for (int kk = 0; kk < 8; ++kk) {
            uint32_t a0[4], a1[4];
            ldsm4(a0, aBase0 + 256 + kk * 32);   // cols [64,128)
            ldsm4(a1, aBase1 + 256 + kk * 32);
#pragma unroll
            for (int nt = 0; nt < 4; ++nt) {
                mma16n8k8(acc[0][nt], a0, B3f[kk * 8 + nt * 2], B3f[kk * 8 + nt * 2 + 1]);
                mma16n8k8(acc[1][nt], a1, B3f[kk * 8 + nt * 2], B3f[kk * 8 + nt * 2 + 1]);
            }
        }

        // ---- layer 4 epilogue ----
        {
            float pr[2][2];
            pr[0][0] = pr[0][1] = pr[1][0] = pr[1][1] = 0.0f;
#pragma unroll
            for (int mt = 0; mt < 2; ++mt)
#pragma unroll
                for (int nt = 0; nt < 4; ++nt) {
                    const int col = nslot * 32 + nt * 8 + t * 2;
                    pr[mt][0] = fmaf(fmaxf(acc[mt][nt][0] + sB3[col], 0.f),     sW4[col],     pr[mt][0]);
                    pr[mt][0] = fmaf(fmaxf(acc[mt][nt][1] + sB3[col + 1], 0.f), sW4[col + 1], pr[mt][0]);
                    pr[mt][1] = fmaf(fmaxf(acc[mt][nt][2] + sB3[col], 0.f),     sW4[col],     pr[mt][1]);
                    pr[mt][1] = fmaf(fmaxf(acc[mt][nt][3] + sB3[col + 1], 0.f), sW4[col + 1], pr[mt][1]);
                }
#pragma unroll
            for (int mt = 0; mt < 2; ++mt) {
                pr[mt][0] += __shfl_xor_sync(0xffffffffu, pr[mt][0], 1);
                pr[mt][0] += __shfl_xor_sync(0xffffffffu, pr[mt][0], 2);
                pr[mt][1] += __shfl_xor_sync(0xffffffffu, pr[mt][1], 1);
                pr[mt][1] += __shfl_xor_sync(0xffffffffu, pr[mt][1], 2);
                if (t == 0) {
                    const int r0 = mslot * 32 + mt * 16 + g;
                    sPart[nslot * 128 + r0] = pr[mt][0];
                    sPart[nslot * 128 + r0 + 8] = pr[mt][1];
                }
            }
        }
        __syncthreads();
        if (tid < 128) out[p0 + tid] = sPart[tid] + sPart[128 + tid] + b4v;
    }
}

// ---------------------------------------------------------------------------
// Launch
// ---------------------------------------------------------------------------
extern "C" void kernel_launch(void* const* d_in, const int* in_sizes, int n_in,
                              void* d_out, int out_size) {
    const float* features = (const float*)d_in[0];
    const float* points   = (const float*)d_in[1];
    const float* kmat     = (const float*)d_in[2];
    const float* rtm      = (const float*)d_in[3];
    const float* Bg       = (const float*)d_in[4];
    const float* W1 = (const float*)d_in[5];
    const float* b1 = (const float*)d_in[6];
    const float* W2 = (const float*)d_in[7];
    const float* b2 = (const float*)d_in[8];
    const float* W3 = (const float*)d_in[9];
    const float* b3 = (const float*)d_in[10];
    const float* W4 = (const float*)d_in[11];
    const float* b4 = (const float*)d_in[12];

    dim3 tb(32, 32);
    dim3 tg(3136 / 32, CHN / 32, BATCH);
    transpose_kernel<<<tg, tb>>>(features, W1, W2, W3);

    cudaFuncSetAttribute(decoder_kernel,
                         cudaFuncAttributeMaxDynamicSharedMemorySize, SMEM_TOTAL);
    decoder_kernel<<<GRID_CTAS, NTHREADS, SMEM_TOTAL>>>(
        points, kmat, rtm, Bg, b1, b2, b3, W4, b4, (float*)d_out);
}